// round 14
// baseline (speedup 1.0000x reference)
#include <cuda_runtime.h>
#include <cuda_fp16.h>
#include <cstdint>
#include <math.h>

// Problem constants (fixed by the dataset)
#define T_TOK 4096
#define H_DIM 1024
#define E_NUM 8
#define I_DIM 1024
#define K_TOP 2
#define NSLOT (T_TOK * K_TOP)   // 8192 (token,expert) assignments
#define NPERS 296               // persistent CTAs: 2 per SM x 148

// ---------------- device scratch ----------------
__device__ int   d_counts[E_NUM];
__device__ int   d_off[E_NUM + 1];
__device__ int   d_pos[E_NUM];
__device__ int   d_a_tok[NSLOT];
__device__ float d_w[NSLOT];
__device__ int   d_slot[NSLOT];
__device__ float d_wslot[NSLOT];               // slot -> combine weight

// compact m-tile list (built by scan_kernel; max 64+7 entries)
__device__ int   d_mt_e[128];
__device__ int   d_mt_m[128];
__device__ int   d_nmt;

// fp16 quantized operands
__device__ __half d_x_h[(size_t)T_TOK * H_DIM];
__device__ __half d_h_h[(size_t)NSLOT * I_DIM];
__device__ __half d_w13_h[(size_t)E_NUM * 2 * I_DIM * H_DIM];
__device__ __half d_w2_h[(size_t)E_NUM * H_DIM * I_DIM];

// ---------------- PTX helpers ----------------
__device__ __forceinline__ uint32_t smem_u32(const void* p) {
    uint32_t a;
    asm("{ .reg .u64 t; cvta.to.shared.u64 t, %1; cvt.u32.u64 %0, t; }" : "=r"(a) : "l"(p));
    return a;
}
#define CP_ASYNC16(dst_u32, src_ptr) \
    asm volatile("cp.async.cg.shared.global [%0], [%1], 16;" :: "r"(dst_u32), "l"(src_ptr))
#define CP_COMMIT() asm volatile("cp.async.commit_group;" ::: "memory")
#define CP_WAIT1()  asm volatile("cp.async.wait_group 1;" ::: "memory")
#define CP_WAIT0()  asm volatile("cp.async.wait_group 0;" ::: "memory")

__device__ __forceinline__ void mma_f16(float* d, const uint32_t* a, const uint32_t* b) {
    asm volatile(
        "mma.sync.aligned.m16n8k16.row.col.f32.f16.f16.f32 "
        "{%0,%1,%2,%3}, {%4,%5,%6,%7}, {%8,%9}, {%0,%1,%2,%3};"
        : "+f"(d[0]), "+f"(d[1]), "+f"(d[2]), "+f"(d[3])
        : "r"(a[0]), "r"(a[1]), "r"(a[2]), "r"(a[3]), "r"(b[0]), "r"(b[1]));
}

__device__ __forceinline__ float gelu_f(float g) {
    return 0.5f * g * (1.0f + erff(g * 0.70710678118654752f));
}

// ---------------- small kernels ----------------
__global__ void init_kernel() {
    int i = threadIdx.x;
    if (i < E_NUM) d_counts[i] = 0;
}

__global__ void router_kernel(const float* __restrict__ logits,
                              const float* __restrict__ scale) {
    int t = blockIdx.x * blockDim.x + threadIdx.x;
    if (t >= T_TOK) return;
    float l[E_NUM];
#pragma unroll
    for (int e = 0; e < E_NUM; e++) l[e] = logits[t * E_NUM + e];
    int e0 = 0; float v0 = l[0];
#pragma unroll
    for (int e = 1; e < E_NUM; e++) if (l[e] > v0) { v0 = l[e]; e0 = e; }
    int e1 = -1; float v1 = -3.0e38f;
#pragma unroll
    for (int e = 0; e < E_NUM; e++) if (e != e0 && l[e] > v1) { v1 = l[e]; e1 = e; }
    float p1 = expf(v1 - v0);
    float inv = 1.0f / (1.0f + p1);
    d_w[t * 2 + 0] = inv * scale[e0];
    d_w[t * 2 + 1] = p1 * inv * scale[e1];
    d_slot[t * 2 + 0] = e0;
    d_slot[t * 2 + 1] = e1;
    atomicAdd(&d_counts[e0], 1);
    atomicAdd(&d_counts[e1], 1);
}

__global__ void scan_kernel() {
    if (threadIdx.x == 0) {
        int acc = 0;
        int nmt = 0;
        for (int e = 0; e < E_NUM; e++) {
            d_off[e] = acc;
            d_pos[e] = acc;
            int cnt = d_counts[e];
            int mt = (cnt + 127) >> 7;
            for (int m = 0; m < mt; m++) {
                d_mt_e[nmt] = e;
                d_mt_m[nmt] = m;
                nmt++;
            }
            acc += cnt;
        }
        d_off[E_NUM] = acc;
        d_nmt = nmt;
    }
}

__global__ void scatter_kernel() {
    int t = blockIdx.x * blockDim.x + threadIdx.x;
    if (t >= T_TOK) return;
#pragma unroll
    for (int k = 0; k < K_TOP; k++) {
        int e = d_slot[t * 2 + k];
        int p = atomicAdd(&d_pos[e], 1);
        d_a_tok[p] = t;
        d_wslot[p] = d_w[t * 2 + k];
        d_slot[t * 2 + k] = p;
    }
}

// ---------------- fp32 -> fp16 quantize (selects dst in device code) ---------
// TARGET 0 additionally zeroes out[] (same thread count: T*H/4 float4s).
template <int TARGET>   // 0: x (+zero out), 1: w13, 2: w2
__global__ void quant_kernel(const float* __restrict__ in, float* __restrict__ out, int n4) {
    int i = blockIdx.x * blockDim.x + threadIdx.x;
    if (i >= n4) return;
    __half* dst = (TARGET == 0) ? d_x_h : (TARGET == 1) ? d_w13_h : d_w2_h;
    float4 v = ((const float4*)in)[i];
    ((half2*)dst)[i * 2 + 0] = half2(__float2half_rn(v.x), __float2half_rn(v.y));
    ((half2*)dst)[i * 2 + 1] = half2(__float2half_rn(v.z), __float2half_rn(v.w));
    if (TARGET == 0)
        ((float4*)out)[i] = make_float4(0.f, 0.f, 0.f, 0.f);
}

// ---------------- persistent grouped GEMM: fp16 mma, fp32 accumulate ---------
// MODE 0 (gemm1 + fused GELU): CTA tile covers 64 h-columns; B rows interleave
//   w1/w3 at 8-row granularity so acc ns=2q holds g and ns=2q+1 holds u for
//   the same (row, h-col); epilogue writes d_h_h = gelu(g)*u (fp16).
// MODE 1 (gemm2 + fused combine): epilogue atomicAdds w_slot * acc into
//   out[token, col].
// Persistent: NPERS CTAs loop over the compact tile list (no empty CTAs,
// no wave quantization). CTA: 128 threads, 4 warps (2m x 2n), warp tile 64x64.
// 3-stage cp.async pipeline, one __syncthreads per chunk + one per tile.
#define SROW 40                      // smem row stride in halves (80 B)
#define BUFB (128 * SROW * 2)        // 10240 bytes per buffer
#define STGB (2 * BUFB)              // 20480 bytes per stage (A, B)
#define NSTG 3

template <int MODE>
__global__ __launch_bounds__(128, 2)
void gemm_tc_kernel(float* __restrict__ out) {
    constexpr int KD = 1024;
    constexpr int NC = 32;
    constexpr int NTN_SHIFT = (MODE == 0) ? 4 : 3;   // 16 / 8 n-tiles
    constexpr int NTN_MASK  = (MODE == 0) ? 15 : 7;

    const __half* __restrict__ Ah = (MODE == 0) ? d_x_h   : d_h_h;
    const __half* __restrict__ Bh = (MODE == 0) ? d_w13_h : d_w2_h;

    extern __shared__ char smc[];
    const uint32_t sbase = smem_u32(smc);

    const int tid = threadIdx.x;
    const int wid = tid >> 5;
    const int lane = tid & 31;
    const int g  = lane >> 2;     // 0..7
    const int tg = lane & 3;      // 0..3
    const int warp_m = wid >> 1;  // 0..1
    const int warp_n = wid & 1;   // 0..1

    const int nmt = d_nmt;
    const int ntiles = nmt << NTN_SHIFT;

    for (int idx = blockIdx.x; idx < ntiles; idx += gridDim.x) {
        const int mt = idx >> NTN_SHIFT;
        const int nt = idx & NTN_MASK;
        const int e = d_mt_e[mt];
        const int m_begin = d_off[e];
        const int m_count = d_off[e + 1] - m_begin;
        const int tile_m = d_mt_m[mt] << 7;
        const int n0 = nt * ((MODE == 0) ? 64 : 128);

        // -------- cp.async mapping: 4 ids/thread, each = (row, 16B-chunk) ----
        const __half *pa[4], *pb[4];
        uint32_t soff[4];
#pragma unroll
        for (int i = 0; i < 4; i++) {
            int id = tid + i * 128;        // 0..511
            int row = id >> 2;             // 0..127
            int c = id & 3;                // 16B chunk
            int mrow = tile_m + row;
            int gslot = m_begin + ((mrow < m_count) ? mrow : 0);
            int arow = (MODE == 0) ? d_a_tok[gslot] : gslot;
            pa[i] = Ah + (size_t)arow * KD + c * 8;
            size_t brow;
            if (MODE == 0) {
                int sub = (row >> 3) & 1;          // 0: w1, 1: w3
                brow = (size_t)e * (2 * I_DIM) + (size_t)sub * I_DIM
                     + n0 + (row >> 4) * 8 + (row & 7);
            } else {
                brow = (size_t)e * H_DIM + n0 + row;
            }
            pb[i] = Bh + brow * KD + c * 8;
            soff[i] = (uint32_t)(row * (SROW * 2) + c * 16);
        }

        float acc[4][8][4];
#pragma unroll
        for (int ms = 0; ms < 4; ms++)
#pragma unroll
            for (int ns = 0; ns < 8; ns++)
#pragma unroll
                for (int q = 0; q < 4; q++) acc[ms][ns][q] = 0.0f;

        // prologue: issue chunks 0 and 1 (stages 0, 1)
#pragma unroll
        for (int cc = 0; cc < 2; cc++) {
            uint32_t st = sbase + cc * STGB;
            int koff = cc * 32;
#pragma unroll
            for (int i = 0; i < 4; i++) {
                CP_ASYNC16(st + 0 * BUFB + soff[i], pa[i] + koff);
                CP_ASYNC16(st + 1 * BUFB + soff[i], pb[i] + koff);
            }
            CP_COMMIT();
        }

        for (int c = 0; c < NC; c++) {
            if (c + 1 < NC) CP_WAIT1(); else CP_WAIT0();
            __syncthreads();

            if (c + 2 < NC) {
                int cc = c + 2;
                uint32_t st = sbase + (cc % NSTG) * STGB;
                int koff = cc * 32;
#pragma unroll
                for (int i = 0; i < 4; i++) {
                    CP_ASYNC16(st + 0 * BUFB + soff[i], pa[i] + koff);
                    CP_ASYNC16(st + 1 * BUFB + soff[i], pb[i] + koff);
                }
                CP_COMMIT();
            }

            const uint32_t* A0 = (const uint32_t*)(smc + (c % NSTG) * STGB);
            const uint32_t* B0 = A0 + BUFB / 4;

#pragma unroll
            for (int ks = 0; ks < 2; ks++) {        // two k16 steps per chunk
                const int kb = ks * 8;              // word offset in 20-word row
                uint32_t af[4][4];
#pragma unroll
                for (int ms = 0; ms < 4; ms++) {
                    int rb = warp_m * 64 + ms * 16;
                    int w0 = (rb + g) * 20 + kb + tg;
                    int w1 = (rb + 8 + g) * 20 + kb + tg;
                    af[ms][0] = A0[w0];     af[ms][1] = A0[w1];
                    af[ms][2] = A0[w0 + 4]; af[ms][3] = A0[w1 + 4];
                }
#pragma unroll
                for (int ns = 0; ns < 8; ns++) {
                    int cb = warp_n * 64 + ns * 8;
                    int wb = (cb + g) * 20 + kb + tg;
                    uint32_t bf[2];
                    bf[0] = B0[wb]; bf[1] = B0[wb + 4];
#pragma unroll
                    for (int ms = 0; ms < 4; ms++)
                        mma_f16(acc[ms][ns], af[ms], bf);
                }
            }
        }

        // -------- epilogue --------
        if (MODE == 0) {
#pragma unroll
            for (int ms = 0; ms < 4; ms++) {
                int r0 = tile_m + warp_m * 64 + ms * 16 + g;
                int r1 = r0 + 8;
#pragma unroll
                for (int q = 0; q < 4; q++) {
                    int col = n0 + (warp_n * 4 + q) * 8 + 2 * tg;
                    float* gv = acc[ms][2 * q];
                    float* uv = acc[ms][2 * q + 1];
                    if (r0 < m_count) {
                        float h0 = gelu_f(gv[0]) * uv[0];
                        float h1 = gelu_f(gv[1]) * uv[1];
                        *(half2*)(d_h_h + (size_t)(m_begin + r0) * I_DIM + col) =
                            half2(__float2half_rn(h0), __float2half_rn(h1));
                    }
                    if (r1 < m_count) {
                        float h2 = gelu_f(gv[2]) * uv[2];
                        float h3 = gelu_f(gv[3]) * uv[3];
                        *(half2*)(d_h_h + (size_t)(m_begin + r1) * I_DIM + col) =
                            half2(__float2half_rn(h2), __float2half_rn(h3));
                    }
                }
            }
        } else {
#pragma unroll
            for (int ms = 0; ms < 4; ms++) {
                int r0 = tile_m + warp_m * 64 + ms * 16 + g;
                int r1 = r0 + 8;
                int t0 = 0, t1 = 0;
                float ws0 = 0.f, ws1 = 0.f;
                if (r0 < m_count) { t0 = d_a_tok[m_begin + r0]; ws0 = d_wslot[m_begin + r0]; }
                if (r1 < m_count) { t1 = d_a_tok[m_begin + r1]; ws1 = d_wslot[m_begin + r1]; }
#pragma unroll
                for (int ns = 0; ns < 8; ns++) {
                    int col = n0 + warp_n * 64 + ns * 8 + 2 * tg;
                    if (r0 < m_count) {
                        float* p = out + (size_t)t0 * H_DIM + col;
                        atomicAdd(p + 0, ws0 * acc[ms][ns][0]);
                        atomicAdd(p + 1, ws0 * acc[ms][ns][1]);
                    }
                    if (r1 < m_count) {
                        float* p = out + (size_t)t1 * H_DIM + col;
                        atomicAdd(p + 0, ws1 * acc[ms][ns][2]);
                        atomicAdd(p + 1, ws1 * acc[ms][ns][3]);
                    }
                }
            }
        }

        // protect stage 0/1 smem reuse by next tile's prologue
        __syncthreads();
    }
}

// ---------------- launch ----------------
extern "C" void kernel_launch(void* const* d_in, const int* in_sizes, int n_in,
                              void* d_out, int out_size) {
    const float* x      = (const float*)d_in[0];
    const float* logits = (const float*)d_in[1];
    const float* scale  = (const float*)d_in[2];
    const float* w13    = (const float*)d_in[3];
    const float* w2     = (const float*)d_in[4];
    float* out = (float*)d_out;

    const int SMEM = NSTG * STGB;   // 61440 bytes
    cudaFuncSetAttribute(gemm_tc_kernel<0>, cudaFuncAttributeMaxDynamicSharedMemorySize, SMEM);
    cudaFuncSetAttribute(gemm_tc_kernel<1>, cudaFuncAttributeMaxDynamicSharedMemorySize, SMEM);

    init_kernel<<<1, 32>>>();
    router_kernel<<<T_TOK / 256, 256>>>(logits, scale);
    scan_kernel<<<1, 32>>>();
    scatter_kernel<<<T_TOK / 256, 256>>>();

    // operand quantization (TARGET 0 also zeroes out[])
    {
        int n4 = T_TOK * H_DIM / 4;
        quant_kernel<0><<<(n4 + 255) / 256, 256>>>(x, out, n4);
    }
    {
        int n4 = E_NUM * 2 * I_DIM * H_DIM / 4;
        quant_kernel<1><<<(n4 + 255) / 256, 256>>>(w13, nullptr, n4);
    }
    {
        int n4 = E_NUM * H_DIM * I_DIM / 4;
        quant_kernel<2><<<(n4 + 255) / 256, 256>>>(w2, nullptr, n4);
    }

    // persistent GEMM1 + fused GELU
    gemm_tc_kernel<0><<<NPERS, 128, SMEM>>>(out);

    // persistent GEMM2 + fused combine
    gemm_tc_kernel<1><<<NPERS, 128, SMEM>>>(out);
}

// round 15
// speedup vs baseline: 1.0128x; 1.0128x over previous
#include <cuda_runtime.h>
#include <cuda_fp16.h>
#include <cstdint>
#include <math.h>

// Problem constants (fixed by the dataset)
#define T_TOK 4096
#define H_DIM 1024
#define E_NUM 8
#define I_DIM 1024
#define K_TOP 2
#define NSLOT (T_TOK * K_TOP)   // 8192 (token,expert) assignments

// ---------------- device scratch ----------------
__device__ int   d_counts[E_NUM];
__device__ int   d_off[E_NUM + 1];
__device__ int   d_pos[E_NUM];
__device__ int   d_a_tok[NSLOT];
__device__ float d_w[NSLOT];
__device__ int   d_slot[NSLOT];
__device__ float d_wslot[NSLOT];               // slot -> combine weight

// fp16 quantized activations (weights stay fp32, converted in-GEMM)
__device__ __half d_x_h[(size_t)T_TOK * H_DIM];
__device__ __half d_h_h[(size_t)NSLOT * I_DIM];

// ---------------- PTX helpers ----------------
__device__ __forceinline__ uint32_t smem_u32(const void* p) {
    uint32_t a;
    asm("{ .reg .u64 t; cvta.to.shared.u64 t, %1; cvt.u32.u64 %0, t; }" : "=r"(a) : "l"(p));
    return a;
}
#define CP_ASYNC16(dst_u32, src_ptr) \
    asm volatile("cp.async.cg.shared.global [%0], [%1], 16;" :: "r"(dst_u32), "l"(src_ptr))
#define CP_COMMIT() asm volatile("cp.async.commit_group;" ::: "memory")
#define CP_WAIT1()  asm volatile("cp.async.wait_group 1;" ::: "memory")
#define CP_WAIT0()  asm volatile("cp.async.wait_group 0;" ::: "memory")

__device__ __forceinline__ void mma_f16(float* d, const uint32_t* a, const uint32_t* b) {
    asm volatile(
        "mma.sync.aligned.m16n8k16.row.col.f32.f16.f16.f32 "
        "{%0,%1,%2,%3}, {%4,%5,%6,%7}, {%8,%9}, {%0,%1,%2,%3};"
        : "+f"(d[0]), "+f"(d[1]), "+f"(d[2]), "+f"(d[3])
        : "r"(a[0]), "r"(a[1]), "r"(a[2]), "r"(a[3]), "r"(b[0]), "r"(b[1]));
}

// pack two fp32 -> half2 {lo, hi} with round-to-nearest (same as __float2half_rn)
__device__ __forceinline__ uint32_t pack_h2(float lo, float hi) {
    uint32_t r;
    asm("cvt.rn.f16x2.f32 %0, %1, %2;" : "=r"(r) : "f"(hi), "f"(lo));
    return r;
}

__device__ __forceinline__ float gelu_f(float g) {
    return 0.5f * g * (1.0f + erff(g * 0.70710678118654752f));
}

// ---------------- small kernels ----------------
__global__ void init_kernel() {
    int i = threadIdx.x;
    if (i < E_NUM) d_counts[i] = 0;
}

__global__ void router_kernel(const float* __restrict__ logits,
                              const float* __restrict__ scale) {
    int t = blockIdx.x * blockDim.x + threadIdx.x;
    if (t >= T_TOK) return;
    float l[E_NUM];
#pragma unroll
    for (int e = 0; e < E_NUM; e++) l[e] = logits[t * E_NUM + e];
    int e0 = 0; float v0 = l[0];
#pragma unroll
    for (int e = 1; e < E_NUM; e++) if (l[e] > v0) { v0 = l[e]; e0 = e; }
    int e1 = -1; float v1 = -3.0e38f;
#pragma unroll
    for (int e = 0; e < E_NUM; e++) if (e != e0 && l[e] > v1) { v1 = l[e]; e1 = e; }
    float p1 = expf(v1 - v0);
    float inv = 1.0f / (1.0f + p1);
    d_w[t * 2 + 0] = inv * scale[e0];
    d_w[t * 2 + 1] = p1 * inv * scale[e1];
    d_slot[t * 2 + 0] = e0;
    d_slot[t * 2 + 1] = e1;
    atomicAdd(&d_counts[e0], 1);
    atomicAdd(&d_counts[e1], 1);
}

__global__ void scan_kernel() {
    if (threadIdx.x == 0) {
        int acc = 0;
        for (int e = 0; e < E_NUM; e++) {
            d_off[e] = acc;
            d_pos[e] = acc;
            acc += d_counts[e];
        }
        d_off[E_NUM] = acc;
    }
}

__global__ void scatter_kernel() {
    int t = blockIdx.x * blockDim.x + threadIdx.x;
    if (t >= T_TOK) return;
#pragma unroll
    for (int k = 0; k < K_TOP; k++) {
        int e = d_slot[t * 2 + k];
        int p = atomicAdd(&d_pos[e], 1);
        d_a_tok[p] = t;
        d_wslot[p] = d_w[t * 2 + k];
        d_slot[t * 2 + k] = p;
    }
}

// ---------------- x -> fp16 + zero out ----------------
__global__ void quant_x_kernel(const float* __restrict__ in, float* __restrict__ out, int n4) {
    int i = blockIdx.x * blockDim.x + threadIdx.x;
    if (i >= n4) return;
    float4 v = ((const float4*)in)[i];
    ((half2*)d_x_h)[i * 2 + 0] = half2(__float2half_rn(v.x), __float2half_rn(v.y));
    ((half2*)d_x_h)[i * 2 + 1] = half2(__float2half_rn(v.z), __float2half_rn(v.w));
    ((float4*)out)[i] = make_float4(0.f, 0.f, 0.f, 0.f);
}

// ---------------- grouped GEMM: fp16 mma, fp32-weight B path -----------------
// A (activations) fp16 in smem (padded rows); B (weights) fp32 in smem with
// SW128 swizzle (128B rows, 16B chunk ^= row&7), converted to fp16 at
// fragment-load time via cvt.rn (bitwise-identical to pre-quantization).
// MODE 0 (gemm1 + fused GELU): CTA covers 64 h-cols; B rows interleave w1/w3
//   at 8-row granularity; acc ns=2q -> g, ns=2q+1 -> u; epilogue writes
//   d_h_h = gelu(g)*u (fp16).
// MODE 1 (gemm2 + fused combine): epilogue atomicAdds w_slot * acc into out.
// CTA: 128 threads, 4 warps (2m x 2n), CTA tile 128x128, warp tile 64x64.
// K = 1024 in 32 chunks of 32; 3-stage cp.async pipeline, 1 sync per chunk.
#define SROW 40                      // A smem row stride in halves (80 B)
#define ABUF (128 * SROW * 2)        // 10240 bytes (A fp16)
#define BBUF (128 * 128)             // 16384 bytes (B fp32, 128B rows)
#define STGB (ABUF + BBUF)           // 26624 bytes per stage
#define NSTG 3

template <int MODE>
__global__ __launch_bounds__(128, 2)
void gemm_tc_kernel(const float* __restrict__ W, float* __restrict__ out) {
    constexpr int KD = 1024;
    constexpr int NC = 32;

    const __half* __restrict__ Ah = (MODE == 0) ? d_x_h : d_h_h;

    extern __shared__ char smc[];
    const uint32_t sbase = smem_u32(smc);

    const int tid = threadIdx.x;
    const int wid = tid >> 5;
    const int lane = tid & 31;
    const int g  = lane >> 2;     // 0..7
    const int tg = lane & 3;      // 0..3
    const int warp_m = wid >> 1;  // 0..1
    const int warp_n = wid & 1;   // 0..1

    const int e = blockIdx.z;
    const int m_begin = d_off[e];
    const int m_count = d_off[e + 1] - m_begin;
    const int tile_m = blockIdx.y * 128;
    if (tile_m >= m_count) return;
    const int n0 = blockIdx.x * ((MODE == 0) ? 64 : 128);

    // -------- A cp.async mapping: 4 ids/thread = (row, 16B chunk of 4) ------
    const __half* pa[4];
    uint32_t soffA[4];
#pragma unroll
    for (int i = 0; i < 4; i++) {
        int id = tid + i * 128;        // 0..511
        int row = id >> 2;             // 0..127
        int c = id & 3;                // 16B chunk (row = 32 halves = 4 chunks)
        int mrow = tile_m + row;
        int gslot = m_begin + ((mrow < m_count) ? mrow : 0);
        int arow = (MODE == 0) ? d_a_tok[gslot] : gslot;
        pa[i] = Ah + (size_t)arow * KD + c * 8;
        soffA[i] = (uint32_t)(row * (SROW * 2) + c * 16);
    }
    // -------- B cp.async mapping: 8 ids/thread = (row, 16B chunk of 8) ------
    const float* pb[8];
    uint32_t soffB[8];
#pragma unroll
    for (int i = 0; i < 8; i++) {
        int id = tid + i * 128;        // 0..1023
        int row = id >> 3;             // 0..127
        int c = id & 7;                // 16B chunk (row = 32 floats = 8 chunks)
        size_t brow;
        if (MODE == 0) {
            int sub = (row >> 3) & 1;          // 0: w1, 1: w3
            brow = (size_t)e * (2 * I_DIM) + (size_t)sub * I_DIM
                 + n0 + (row >> 4) * 8 + (row & 7);
        } else {
            brow = (size_t)e * H_DIM + n0 + row;
        }
        pb[i] = W + brow * KD + c * 4;
        soffB[i] = (uint32_t)(ABUF + row * 128 + ((c ^ (row & 7)) * 16));
    }

    float acc[4][8][4];
#pragma unroll
    for (int ms = 0; ms < 4; ms++)
#pragma unroll
        for (int ns = 0; ns < 8; ns++)
#pragma unroll
            for (int q = 0; q < 4; q++) acc[ms][ns][q] = 0.0f;

    // prologue: issue chunks 0 and 1 (stages 0, 1)
#pragma unroll
    for (int cc = 0; cc < 2; cc++) {
        uint32_t st = sbase + cc * STGB;
        int koff = cc * 32;
#pragma unroll
        for (int i = 0; i < 4; i++) CP_ASYNC16(st + soffA[i], pa[i] + koff);
#pragma unroll
        for (int i = 0; i < 8; i++) CP_ASYNC16(st + soffB[i], pb[i] + koff);
        CP_COMMIT();
    }

    for (int c = 0; c < NC; c++) {
        if (c + 1 < NC) CP_WAIT1(); else CP_WAIT0();
        __syncthreads();

        if (c + 2 < NC) {
            int cc = c + 2;
            uint32_t st = sbase + (cc % NSTG) * STGB;
            int koff = cc * 32;
#pragma unroll
            for (int i = 0; i < 4; i++) CP_ASYNC16(st + soffA[i], pa[i] + koff);
#pragma unroll
            for (int i = 0; i < 8; i++) CP_ASYNC16(st + soffB[i], pb[i] + koff);
            CP_COMMIT();
        }

        const char* stg = smc + (c % NSTG) * STGB;
        const uint32_t* A0 = (const uint32_t*)stg;
        const float*    B0 = (const float*)(stg + ABUF);

#pragma unroll
        for (int ks = 0; ks < 2; ks++) {        // two k16 steps per 32-chunk
            const int kb = ks * 8;              // A word offset in 20-word row
            uint32_t af[4][4];
#pragma unroll
            for (int ms = 0; ms < 4; ms++) {
                int rb = warp_m * 64 + ms * 16;
                int w0 = (rb + g) * 20 + kb + tg;
                int w1 = (rb + 8 + g) * 20 + kb + tg;
                af[ms][0] = A0[w0];     af[ms][1] = A0[w1];
                af[ms][2] = A0[w0 + 4]; af[ms][3] = A0[w1 + 4];
            }
#pragma unroll
            for (int ns = 0; ns < 8; ns++) {
                int rw = warp_n * 64 + ns * 8 + g;       // B row (output col)
                int sw = rw & 7;
                int c0 = 4 * ks + (tg >> 1);             // 16B chunk of k pair
                int intra = (2 * tg) & 3;                // word within chunk
                const float* base = B0 + rw * 32;
                float2 f0 = *(const float2*)(base + 4 * (c0 ^ sw) + intra);
                float2 f1 = *(const float2*)(base + 4 * ((c0 + 2) ^ sw) + intra);
                uint32_t bf[2];
                bf[0] = pack_h2(f0.x, f0.y);
                bf[1] = pack_h2(f1.x, f1.y);
#pragma unroll
                for (int ms = 0; ms < 4; ms++)
                    mma_f16(acc[ms][ns], af[ms], bf);
            }
        }
    }

    // -------- epilogue --------
    if (MODE == 0) {
#pragma unroll
        for (int ms = 0; ms < 4; ms++) {
            int r0 = tile_m + warp_m * 64 + ms * 16 + g;
            int r1 = r0 + 8;
#pragma unroll
            for (int q = 0; q < 4; q++) {
                int col = n0 + (warp_n * 4 + q) * 8 + 2 * tg;
                float* gv = acc[ms][2 * q];
                float* uv = acc[ms][2 * q + 1];
                if (r0 < m_count) {
                    float h0 = gelu_f(gv[0]) * uv[0];
                    float h1 = gelu_f(gv[1]) * uv[1];
                    *(half2*)(d_h_h + (size_t)(m_begin + r0) * I_DIM + col) =
                        half2(__float2half_rn(h0), __float2half_rn(h1));
                }
                if (r1 < m_count) {
                    float h2 = gelu_f(gv[2]) * uv[2];
                    float h3 = gelu_f(gv[3]) * uv[3];
                    *(half2*)(d_h_h + (size_t)(m_begin + r1) * I_DIM + col) =
                        half2(__float2half_rn(h2), __float2half_rn(h3));
                }
            }
        }
    } else {
#pragma unroll
        for (int ms = 0; ms < 4; ms++) {
            int r0 = tile_m + warp_m * 64 + ms * 16 + g;
            int r1 = r0 + 8;
            int t0 = 0, t1 = 0;
            float ws0 = 0.f, ws1 = 0.f;
            if (r0 < m_count) { t0 = d_a_tok[m_begin + r0]; ws0 = d_wslot[m_begin + r0]; }
            if (r1 < m_count) { t1 = d_a_tok[m_begin + r1]; ws1 = d_wslot[m_begin + r1]; }
#pragma unroll
            for (int ns = 0; ns < 8; ns++) {
                int col = n0 + warp_n * 64 + ns * 8 + 2 * tg;
                if (r0 < m_count) {
                    float* p = out + (size_t)t0 * H_DIM + col;
                    atomicAdd(p + 0, ws0 * acc[ms][ns][0]);
                    atomicAdd(p + 1, ws0 * acc[ms][ns][1]);
                }
                if (r1 < m_count) {
                    float* p = out + (size_t)t1 * H_DIM + col;
                    atomicAdd(p + 0, ws1 * acc[ms][ns][2]);
                    atomicAdd(p + 1, ws1 * acc[ms][ns][3]);
                }
            }
        }
    }
}

// ---------------- launch ----------------
extern "C" void kernel_launch(void* const* d_in, const int* in_sizes, int n_in,
                              void* d_out, int out_size) {
    const float* x      = (const float*)d_in[0];
    const float* logits = (const float*)d_in[1];
    const float* scale  = (const float*)d_in[2];
    const float* w13    = (const float*)d_in[3];
    const float* w2     = (const float*)d_in[4];
    float* out = (float*)d_out;

    const int SMEM = NSTG * STGB;   // 79872 bytes
    cudaFuncSetAttribute(gemm_tc_kernel<0>, cudaFuncAttributeMaxDynamicSharedMemorySize, SMEM);
    cudaFuncSetAttribute(gemm_tc_kernel<1>, cudaFuncAttributeMaxDynamicSharedMemorySize, SMEM);

    init_kernel<<<1, 32>>>();
    router_kernel<<<T_TOK / 256, 256>>>(logits, scale);
    scan_kernel<<<1, 32>>>();
    scatter_kernel<<<T_TOK / 256, 256>>>();

    // x -> fp16 (+ zero out). Weights are NOT pre-quantized (converted in-GEMM).
    {
        int n4 = T_TOK * H_DIM / 4;
        quant_x_kernel<<<(n4 + 255) / 256, 256>>>(x, out, n4);
    }

    // GEMM1 + fused GELU: 16 n-tiles of 64 h-cols each
    gemm_tc_kernel<0><<<dim3(16, 32, E_NUM), 128, SMEM>>>(w13, out);

    // GEMM2 + fused combine: 8 n-tiles of 128 cols
    gemm_tc_kernel<1><<<dim3(8, 32, E_NUM), 128, SMEM>>>(w2, out);
}

// round 17
// speedup vs baseline: 1.0735x; 1.0600x over previous
#include <cuda_runtime.h>
#include <cuda_fp16.h>
#include <cstdint>
#include <math.h>

// Problem constants (fixed by the dataset)
#define T_TOK 4096
#define H_DIM 1024
#define E_NUM 8
#define I_DIM 1024
#define K_TOP 2
#define CAP   4096               // per-expert slot capacity (max possible count)
#define NSLOTC (E_NUM * CAP)     // 32768 capacity slots

// ---------------- device scratch ----------------
__device__ int   d_cnt[E_NUM];
__device__ int   d_a_tok[NSLOTC];              // slot -> token id
__device__ float d_wslot[NSLOTC];              // slot -> combine weight

// fp16 quantized operands
__device__ __half d_x_h[(size_t)T_TOK * H_DIM];
__device__ __half d_h_h[(size_t)NSLOTC * I_DIM];   // capacity layout (64 MB)
__device__ __half d_w13_h[(size_t)E_NUM * 2 * I_DIM * H_DIM];
__device__ __half d_w2_h[(size_t)E_NUM * H_DIM * I_DIM];

// ---------------- PTX helpers ----------------
__device__ __forceinline__ uint32_t smem_u32(const void* p) {
    uint32_t a;
    asm("{ .reg .u64 t; cvta.to.shared.u64 t, %1; cvt.u32.u64 %0, t; }" : "=r"(a) : "l"(p));
    return a;
}
#define CP_ASYNC16(dst_u32, src_ptr) \
    asm volatile("cp.async.cg.shared.global [%0], [%1], 16;" :: "r"(dst_u32), "l"(src_ptr))
#define CP_COMMIT() asm volatile("cp.async.commit_group;" ::: "memory")
#define CP_WAIT1()  asm volatile("cp.async.wait_group 1;" ::: "memory")
#define CP_WAIT0()  asm volatile("cp.async.wait_group 0;" ::: "memory")

__device__ __forceinline__ void mma_f16(float* d, const uint32_t* a, const uint32_t* b) {
    asm volatile(
        "mma.sync.aligned.m16n8k16.row.col.f32.f16.f16.f32 "
        "{%0,%1,%2,%3}, {%4,%5,%6,%7}, {%8,%9}, {%0,%1,%2,%3};"
        : "+f"(d[0]), "+f"(d[1]), "+f"(d[2]), "+f"(d[3])
        : "r"(a[0]), "r"(a[1]), "r"(a[2]), "r"(a[3]), "r"(b[0]), "r"(b[1]));
}

__device__ __forceinline__ float gelu_f(float g) {
    return 0.5f * g * (1.0f + erff(g * 0.70710678118654752f));
}

// ---------------- fused quantization + zero-out + counter init ---------------
// One launch: [w13 fp32->fp16 | w2 fp32->fp16 | x fp32->fp16 + zero out].
// Block 0 also zeroes the per-expert counters (this kernel precedes routing
// on the same stream, so ordering is guaranteed).
#define W13_4 (E_NUM * 2 * I_DIM * H_DIM / 4)   // 4194304 float4s
#define W2_4  (E_NUM * H_DIM * I_DIM / 4)       // 2097152
#define X_4   (T_TOK * H_DIM / 4)               // 1048576
#define QTOT  (W13_4 + W2_4 + X_4)              // 7340032

__global__ void quant_all_kernel(const float* __restrict__ x,
                                 const float* __restrict__ w13,
                                 const float* __restrict__ w2,
                                 float* __restrict__ out) {
    int i = blockIdx.x * blockDim.x + threadIdx.x;
    if (blockIdx.x == 0 && threadIdx.x < E_NUM) d_cnt[threadIdx.x] = 0;
    if (i >= QTOT) return;
    const float* src;
    __half* dst;
    int j;
    if (i < W13_4)              { j = i;                 src = w13; dst = d_w13_h; }
    else if (i < W13_4 + W2_4)  { j = i - W13_4;         src = w2;  dst = d_w2_h; }
    else                        { j = i - W13_4 - W2_4;  src = x;   dst = d_x_h;
                                  ((float4*)out)[j] = make_float4(0.f, 0.f, 0.f, 0.f); }
    float4 v = ((const float4*)src)[j];
    ((half2*)dst)[j * 2 + 0] = half2(__float2half_rn(v.x), __float2half_rn(v.y));
    ((half2*)dst)[j * 2 + 1] = half2(__float2half_rn(v.z), __float2half_rn(v.w));
}

// ---------------- fused router + scatter (capacity slots, no scan) -----------
__global__ void router_scatter_kernel(const float* __restrict__ logits,
                                      const float* __restrict__ scale) {
    int t = blockIdx.x * blockDim.x + threadIdx.x;
    if (t >= T_TOK) return;
    float l[E_NUM];
#pragma unroll
    for (int e = 0; e < E_NUM; e++) l[e] = logits[t * E_NUM + e];
    int e0 = 0; float v0 = l[0];
#pragma unroll
    for (int e = 1; e < E_NUM; e++) if (l[e] > v0) { v0 = l[e]; e0 = e; }
    int e1 = -1; float v1 = -3.0e38f;
#pragma unroll
    for (int e = 0; e < E_NUM; e++) if (e != e0 && l[e] > v1) { v1 = l[e]; e1 = e; }
    // softmax denominator cancels in dispatch = gate / renorm
    float p1 = expf(v1 - v0);
    float inv = 1.0f / (1.0f + p1);
    float w0 = inv * scale[e0];
    float w1 = p1 * inv * scale[e1];
    int r0 = atomicAdd(&d_cnt[e0], 1);
    int s0 = (e0 << 12) + r0;
    d_a_tok[s0] = t;
    d_wslot[s0] = w0;
    int r1 = atomicAdd(&d_cnt[e1], 1);
    int s1 = (e1 << 12) + r1;
    d_a_tok[s1] = t;
    d_wslot[s1] = w1;
}

// ---------------- grouped GEMM: fp16 single-mma, fp32 accumulate -------------
// MODE 0 (gemm1 + fused GELU): each CTA covers 64 h-columns. The 128-row B tile
//   interleaves w1/w3 at 8-row granularity: smem B row r -> source row
//   e*2048 + ((r>>3)&1)*1024 + n0 + (r>>4)*8 + (r&7).  In-thread acc slice
//   ns=2q holds g, ns=2q+1 holds u for the SAME output (row, h-col) ->
//   epilogue writes d_h_h = gelu(g)*u directly (fp16).
// MODE 1 (gemm2 + fused combine): epilogue atomicAdds w_slot * acc into
//   out[token, col].
// Capacity slots: m_begin = e*4096, m_count = d_cnt[e] (no prefix scan).
// CTA: 128 threads, 4 warps (2m x 2n), CTA tile 128x128, warp tile 64x64.
// 3-stage cp.async pipeline (16B ops), one __syncthreads per chunk.
#define SROW 40                      // smem row stride in halves (80 B, 16B-mult)
#define BUFB (128 * SROW * 2)        // 10240 bytes per buffer
#define STGB (2 * BUFB)              // 20480 bytes per stage (A, B)
#define NSTG 3

template <int MODE>
__global__ __launch_bounds__(128, 2)
void gemm_tc_kernel(float* __restrict__ out) {
    constexpr int KD = 1024;
    constexpr int NC = 32;

    const __half* __restrict__ Ah = (MODE == 0) ? d_x_h   : d_h_h;
    const __half* __restrict__ Bh = (MODE == 0) ? d_w13_h : d_w2_h;

    extern __shared__ char smc[];
    const uint32_t sbase = smem_u32(smc);

    const int tid = threadIdx.x;
    const int wid = tid >> 5;
    const int lane = tid & 31;
    const int g  = lane >> 2;     // 0..7
    const int tg = lane & 3;      // 0..3
    const int warp_m = wid >> 1;  // 0..1
    const int warp_n = wid & 1;   // 0..1

    const int e = blockIdx.z;
    const int m_begin = e << 12;            // capacity layout
    const int m_count = d_cnt[e];
    const int tile_m = blockIdx.y * 128;
    if (tile_m >= m_count) return;
    // MODE 0: n0 = base h-column (64 per CTA). MODE 1: n0 = base out-column.
    const int n0 = blockIdx.x * ((MODE == 0) ? 64 : 128);

    // -------- cp.async mapping: 4 ids/thread, each = (row, 16B-chunk) --------
    const __half *pa[4], *pb[4];
    uint32_t soff[4];
#pragma unroll
    for (int i = 0; i < 4; i++) {
        int id = tid + i * 128;        // 0..511
        int row = id >> 2;             // 0..127
        int c = id & 3;                // 16B chunk
        int mrow = tile_m + row;
        int gslot = m_begin + ((mrow < m_count) ? mrow : 0);
        int arow = (MODE == 0) ? d_a_tok[gslot] : gslot;
        pa[i] = Ah + (size_t)arow * KD + c * 8;
        size_t brow;
        if (MODE == 0) {
            int sub = (row >> 3) & 1;          // 0: w1, 1: w3
            brow = (size_t)e * (2 * I_DIM) + (size_t)sub * I_DIM
                 + n0 + (row >> 4) * 8 + (row & 7);
        } else {
            brow = (size_t)e * H_DIM + n0 + row;
        }
        pb[i] = Bh + brow * KD + c * 8;
        soff[i] = (uint32_t)(row * (SROW * 2) + c * 16);
    }

    float acc[4][8][4];
#pragma unroll
    for (int ms = 0; ms < 4; ms++)
#pragma unroll
        for (int ns = 0; ns < 8; ns++)
#pragma unroll
            for (int q = 0; q < 4; q++) acc[ms][ns][q] = 0.0f;

    // prologue: issue chunks 0 and 1
#pragma unroll
    for (int cc = 0; cc < 2; cc++) {
        uint32_t st = sbase + cc * STGB;
        int koff = cc * 32;
#pragma unroll
        for (int i = 0; i < 4; i++) {
            CP_ASYNC16(st + 0 * BUFB + soff[i], pa[i] + koff);
            CP_ASYNC16(st + 1 * BUFB + soff[i], pb[i] + koff);
        }
        CP_COMMIT();
    }

    for (int c = 0; c < NC; c++) {
        if (c + 1 < NC) CP_WAIT1(); else CP_WAIT0();
        __syncthreads();   // all warps done with stage (c+2)%3 from iteration c-1

        if (c + 2 < NC) {
            int cc = c + 2;
            uint32_t st = sbase + (cc % NSTG) * STGB;
            int koff = cc * 32;
#pragma unroll
            for (int i = 0; i < 4; i++) {
                CP_ASYNC16(st + 0 * BUFB + soff[i], pa[i] + koff);
                CP_ASYNC16(st + 1 * BUFB + soff[i], pb[i] + koff);
            }
            CP_COMMIT();
        }

        const uint32_t* A0 = (const uint32_t*)(smc + (c % NSTG) * STGB);
        const uint32_t* B0 = A0 + BUFB / 4;

#pragma unroll
        for (int ks = 0; ks < 2; ks++) {        // two k16 steps per 32-chunk
            const int kb = ks * 8;              // word offset in 20-word row
            uint32_t af[4][4];
#pragma unroll
            for (int ms = 0; ms < 4; ms++) {
                int rb = warp_m * 64 + ms * 16;
                int w0 = (rb + g) * 20 + kb + tg;
                int w1 = (rb + 8 + g) * 20 + kb + tg;
                af[ms][0] = A0[w0];     af[ms][1] = A0[w1];
                af[ms][2] = A0[w0 + 4]; af[ms][3] = A0[w1 + 4];
            }
#pragma unroll
            for (int ns = 0; ns < 8; ns++) {
                int cb = warp_n * 64 + ns * 8;
                int wb = (cb + g) * 20 + kb + tg;
                uint32_t bf[2];
                bf[0] = B0[wb]; bf[1] = B0[wb + 4];
#pragma unroll
                for (int ms = 0; ms < 4; ms++)
                    mma_f16(acc[ms][ns], af[ms], bf);
            }
        }
    }

    // -------- epilogue --------
    if (MODE == 0) {
        // acc[ms][2q] = g, acc[ms][2q+1] = u for h-col n0+(warp_n*4+q)*8+2tg
#pragma unroll
        for (int ms = 0; ms < 4; ms++) {
            int r0 = tile_m + warp_m * 64 + ms * 16 + g;
            int r1 = r0 + 8;
#pragma unroll
            for (int q = 0; q < 4; q++) {
                int col = n0 + (warp_n * 4 + q) * 8 + 2 * tg;
                float* gv = acc[ms][2 * q];
                float* uv = acc[ms][2 * q + 1];
                if (r0 < m_count) {
                    float h0 = gelu_f(gv[0]) * uv[0];
                    float h1 = gelu_f(gv[1]) * uv[1];
                    *(half2*)(d_h_h + (size_t)(m_begin + r0) * I_DIM + col) =
                        half2(__float2half_rn(h0), __float2half_rn(h1));
                }
                if (r1 < m_count) {
                    float h2 = gelu_f(gv[2]) * uv[2];
                    float h3 = gelu_f(gv[3]) * uv[3];
                    *(half2*)(d_h_h + (size_t)(m_begin + r1) * I_DIM + col) =
                        half2(__float2half_rn(h2), __float2half_rn(h3));
                }
            }
        }
    } else {
        // fused combine: out[tok, col] += w_slot * acc
#pragma unroll
        for (int ms = 0; ms < 4; ms++) {
            int r0 = tile_m + warp_m * 64 + ms * 16 + g;
            int r1 = r0 + 8;
            int t0 = 0, t1 = 0;
            float ws0 = 0.f, ws1 = 0.f;
            if (r0 < m_count) { t0 = d_a_tok[m_begin + r0]; ws0 = d_wslot[m_begin + r0]; }
            if (r1 < m_count) { t1 = d_a_tok[m_begin + r1]; ws1 = d_wslot[m_begin + r1]; }
#pragma unroll
            for (int ns = 0; ns < 8; ns++) {
                int col = n0 + warp_n * 64 + ns * 8 + 2 * tg;
                if (r0 < m_count) {
                    float* p = out + (size_t)t0 * H_DIM + col;
                    atomicAdd(p + 0, ws0 * acc[ms][ns][0]);
                    atomicAdd(p + 1, ws0 * acc[ms][ns][1]);
                }
                if (r1 < m_count) {
                    float* p = out + (size_t)t1 * H_DIM + col;
                    atomicAdd(p + 0, ws1 * acc[ms][ns][2]);
                    atomicAdd(p + 1, ws1 * acc[ms][ns][3]);
                }
            }
        }
    }
}

// ---------------- launch ----------------
extern "C" void kernel_launch(void* const* d_in, const int* in_sizes, int n_in,
                              void* d_out, int out_size) {
    const float* x      = (const float*)d_in[0];
    const float* logits = (const float*)d_in[1];
    const float* scale  = (const float*)d_in[2];
    const float* w13    = (const float*)d_in[3];
    const float* w2     = (const float*)d_in[4];
    float* out = (float*)d_out;

    const int SMEM = NSTG * STGB;   // 61440 bytes
    cudaFuncSetAttribute(gemm_tc_kernel<0>, cudaFuncAttributeMaxDynamicSharedMemorySize, SMEM);
    cudaFuncSetAttribute(gemm_tc_kernel<1>, cudaFuncAttributeMaxDynamicSharedMemorySize, SMEM);

    // 1) fused quantization (w13|w2|x) + zero out + zero counters
    quant_all_kernel<<<(QTOT + 255) / 256, 256>>>(x, w13, w2, out);

    // 2) fused router + scatter (capacity slots, no prefix scan)
    router_scatter_kernel<<<T_TOK / 256, 256>>>(logits, scale);

    // 3) GEMM1 + fused GELU: 16 n-tiles of 64 h-cols each
    gemm_tc_kernel<0><<<dim3(16, 32, E_NUM), 128, SMEM>>>(out);

    // 4) GEMM2 + fused combine: 8 n-tiles of 128 cols
    gemm_tc_kernel<1><<<dim3(8, 32, E_NUM), 128, SMEM>>>(out);
}